// round 10
// baseline (speedup 1.0000x reference)
#include <cuda_runtime.h>
#include <cuda_fp16.h>
#include <cstdint>
#include <cstring>

// ---------------- constants ----------------
#define ZT      128          // z rows per tile
#define NTH     256          // 8 warps: 4 row-groups x 2 col-groups (32x32 tiles)
#define NCHUNK  33           // circulant-difference chunks d=0..32
#define NPERS   296          // persistent CTAs (2 per SM x 148)
#define NTILES  1024         // Z / ZT

#define FH_STRIDE 208        // bytes per fp16 f row (104 halves, 96 used)

// smem layout (bytes)
#define OFF_B    0                            // 2 x 8KB B tiles
#define OFF_F0   16384                        // fp16 f tile (row-doubled)
#define OFF_F1   (16384 + ZT * FH_STRIDE)     // fp16 f tile shifted by one col
#define SMEM_TOTAL (OFF_F1 + ZT * FH_STRIDE)  // 69632

// scratch
__device__ float g_M[4][262144];                             // four w-quarter partials
__device__ __align__(1024) unsigned char g_B[NCHUNK * 8192]; // pre-swizzled fp16 chunks

// ---------------- helpers ----------------
__device__ __forceinline__ uint32_t smem_u32(const void* p) {
    uint32_t a;
    asm("{ .reg .u64 t; cvta.to.shared.u64 t, %1; cvt.u32.u64 %0, t; }"
        : "=r"(a) : "l"(p));
    return a;
}

__device__ __forceinline__ uint32_t h2u(float lo, float hi) {
    __half2 h = __floats2half2_rn(lo, hi);
    uint32_t u;
    memcpy(&u, &h, 4);
    return u;
}

__device__ __forceinline__ uint32_t mulh2(uint32_t a, uint32_t b) {
    uint32_t d;
    asm("mul.rn.f16x2 %0, %1, %2;" : "=r"(d) : "r"(a), "r"(b));
    return d;
}

__device__ __forceinline__ void cpa16(uint32_t s, const void* g) {
    asm volatile("cp.async.cg.shared.global [%0], [%1], 16;" :: "r"(s), "l"(g) : "memory");
}

__device__ __forceinline__ void ldsm4t(uint32_t* r, uint32_t addr) {
    asm volatile(
        "ldmatrix.sync.aligned.m8n8.x4.trans.shared.b16 {%0,%1,%2,%3}, [%4];"
        : "=r"(r[0]), "=r"(r[1]), "=r"(r[2]), "=r"(r[3]) : "r"(addr));
}

__device__ __forceinline__ void mma16816(float* d,
                                         uint32_t a0, uint32_t a1, uint32_t a2, uint32_t a3,
                                         uint32_t b0, uint32_t b1) {
    asm volatile(
        "mma.sync.aligned.m16n8k16.row.col.f32.f16.f16.f32 "
        "{%0,%1,%2,%3}, {%4,%5,%6,%7}, {%8,%9}, {%0,%1,%2,%3};"
        : "+f"(d[0]), "+f"(d[1]), "+f"(d[2]), "+f"(d[3])
        : "r"(a0), "r"(a1), "r"(a2), "r"(a3), "r"(b0), "r"(b1));
}

// ---------------- prep 1: four w-quarter partial sums (MLP-friendly) ----------------
extern "C" __global__ void lts_prep1(const float* __restrict__ mix,
                                     const float* __restrict__ wgt) {
    __shared__ float ws[8];
    const int quarter = blockIdx.x >> 9;        // 0..3
    const int blk     = blockIdx.x & 511;
    if (threadIdx.x < 8) ws[threadIdx.x] = wgt[quarter * 8 + threadIdx.x];
    __syncthreads();

    size_t idx = ((size_t)blk * 128 + threadIdx.x) * 4;
    float4 s = make_float4(0.f, 0.f, 0.f, 0.f);
#pragma unroll
    for (int w = 0; w < 8; ++w) {
        float4 m = __ldg((const float4*)(mix + (size_t)(quarter * 8 + w) * 262144 + idx));
        float c = ws[w];
        s.x += c * m.x; s.y += c * m.y; s.z += c * m.z; s.w += c * m.w;
    }
    *(float4*)(&g_M[quarter][idx]) = s;
}

// ---------------- prep 2: fold symmetric pairs, fp16 swizzled ----------------
extern "C" __global__ void lts_prep2() {
    int t = blockIdx.x * 256 + threadIdx.x;     // < 33*4096
    int d = t >> 12;
    int rem = t & 4095;
    int c = rem >> 6;
    int k = rem & 63;
    int j2 = (c + d) & 63;

    int i1 = k * 4096 + c * 64 + j2;
    int i2 = k * 4096 + j2 * 64 + c;
    float v = (g_M[0][i1] + g_M[1][i1]) + (g_M[2][i1] + g_M[3][i1]);
    if (d > 0) v += (g_M[0][i2] + g_M[1][i2]) + (g_M[2][i2] + g_M[3][i2]);
    if (d == 32) v *= 0.5f;

    unsigned short h;
    {
        __half hh = __float2half_rn(v);
        memcpy(&h, &hh, 2);
    }
    uint32_t off = (uint32_t)c * 128 + (uint32_t)k * 2;
    off ^= ((uint32_t)(c & 7)) << 4;            // SW128-style swizzle
    *(unsigned short*)(g_B + (size_t)d * 8192 + off) = h;
}

// ---------------- main kernel (persistent: NPERS CTAs, stride-assigned tiles) -------
extern "C" __global__ void __launch_bounds__(NTH, 2)
lts_main(const float* __restrict__ f, float* __restrict__ out) {
    extern __shared__ __align__(1024) unsigned char smem[];
    const uint32_t sb = smem_u32(smem);

    const int tid  = threadIdx.x;
    const int wid  = tid >> 5;
    const int lane = tid & 31;

    const int rg = wid & 3;                   // row group: rows rg*32 .. rg*32+31
    const int cg = wid >> 2;                  // col group: cols cg*32 .. cg*32+31
    const int g  = lane >> 2;                 // row within group 0..7
    const int c  = lane & 3;                  // col pair 0..3

    // ldmatrix address components (buffer-local)
    const uint32_t row_base = (lane & 7) + 8 * ((lane >> 3) & 1);
    const uint32_t n0_base  = 8 * (lane >> 4);
    const uint32_t raw      = row_base * 128 + n0_base * 2;
    const uint32_t xconst   = (row_base & 7) << 4;

    for (int tile = blockIdx.x; tile < NTILES; tile += NPERS) {
        const int z0 = tile * ZT;

        // fence: previous tile's chunk-32 ldmatrix (buf0) and F reads must finish
        __syncthreads();

        // ---- prefetch B chunk 0
        {
            uint32_t dst = sb + OFF_B + tid * 32;
            const unsigned char* src = g_B + tid * 32;
            cpa16(dst, src); cpa16(dst + 16, src + 16);
            asm volatile("cp.async.commit_group;" ::: "memory");
        }

        // ---- fill F0: fp16 f tile [ZT x 96] (cols 64..95 dup 0..31), pad zero
        {
            const float4* src = (const float4*)(f + (size_t)z0 * 64);
#pragma unroll
            for (int q = 0; q < (ZT * 16) / NTH; ++q) {
                int idx = tid + q * NTH;
                int row = idx >> 4;
                int c4  = idx & 15;
                float4 v = src[idx];
                uint32_t w0 = h2u(v.x, v.y), w1 = h2u(v.z, v.w);
                uint32_t* p = (uint32_t*)(smem + OFF_F0 + row * FH_STRIDE + c4 * 8);
                p[0] = w0; p[1] = w1;
                if (c4 < 8) {
                    uint32_t* pd = (uint32_t*)(smem + OFF_F0 + row * FH_STRIDE + 128 + c4 * 8);
                    pd[0] = w0; pd[1] = w1;
                }
            }
#pragma unroll
            for (int q = 0; q < (ZT * 4) / NTH; ++q) {
                int idx = tid + q * NTH;
                int row = idx >> 2;
                int w   = idx & 3;
                *(uint32_t*)(smem + OFF_F0 + row * FH_STRIDE + 192 + w * 4) = 0;
            }
        }
        __syncthreads();

        // ---- build F1 (shifted by one half) via funnel shift of F0 words
        {
#pragma unroll
            for (int q = 0; q < (ZT * 48) / NTH; ++q) {
                int idx = tid + q * NTH;
                int row = idx / 48;
                int w   = idx - row * 48;
                const uint32_t* pr = (const uint32_t*)(smem + OFF_F0 + row * FH_STRIDE + w * 4);
                uint32_t a = pr[0], b = pr[1];
                *(uint32_t*)(smem + OFF_F1 + row * FH_STRIDE + w * 4) =
                    __funnelshift_r(a, b, 16);
            }
        }

        // fixed factors: half2 at cols (16s+2c,+1)[a] and (+8,+9)[b], 4 rows (2m x 2h)
        uint32_t fja[2][2][4], fjb[2][2][4];
#pragma unroll
        for (int m = 0; m < 2; ++m)
#pragma unroll
            for (int h = 0; h < 2; ++h) {
                int row = rg * 32 + m * 16 + h * 8 + g;
                const unsigned char* bp = smem + OFF_F0 + row * FH_STRIDE + c * 4;
#pragma unroll
                for (int s = 0; s < 4; ++s) {
                    fja[m][h][s] = *(const uint32_t*)(bp + s * 32);
                    fjb[m][h][s] = *(const uint32_t*)(bp + s * 32 + 16);
                }
            }
        __syncthreads();   // F1 visible

        float acc[2][4][4];
#pragma unroll
        for (int m = 0; m < 2; ++m)
#pragma unroll
            for (int p = 0; p < 4; ++p)
#pragma unroll
                for (int e = 0; e < 4; ++e) acc[m][p][e] = 0.f;

        // ---- chunk loop d = 0..32
#pragma unroll 1
        for (int d = 0; d < NCHUNK; ++d) {
            const uint32_t bbuf = sb + OFF_B + (uint32_t)(d & 1) * 8192;

            asm volatile("cp.async.wait_group 0;" ::: "memory");
            __syncthreads();

            if (d + 1 < NCHUNK) {
                uint32_t dst = sb + OFF_B + (uint32_t)((d + 1) & 1) * 8192 + tid * 32;
                const unsigned char* src = g_B + (size_t)(d + 1) * 8192 + tid * 32;
                cpa16(dst, src); cpa16(dst + 16, src + 16);
                asm volatile("cp.async.commit_group;" ::: "memory");
            }

            const int off_tile = (d & 1) ? (OFF_F1 + (d - 1) * 2) : (OFF_F0 + d * 2);
            const unsigned char* u0base = smem + off_tile + (rg * 32 + g) * FH_STRIDE + c * 4;

            // per k-step: A fragments (8 LDS + 8 HMUL2), 2 ldmatrix, 8 MMA
#pragma unroll
            for (int s = 0; s < 4; ++s) {
                uint32_t af[2][4];
#pragma unroll
                for (int m = 0; m < 2; ++m) {
                    const unsigned char* u0 = u0base + m * (16 * FH_STRIDE) + s * 32;
                    const unsigned char* u1 = u0 + 8 * FH_STRIDE;
                    af[m][0] = mulh2(fja[m][0][s], *(const uint32_t*)(u0));
                    af[m][1] = mulh2(fja[m][1][s], *(const uint32_t*)(u1));
                    af[m][2] = mulh2(fjb[m][0][s], *(const uint32_t*)(u0 + 16));
                    af[m][3] = mulh2(fjb[m][1][s], *(const uint32_t*)(u1 + 16));
                }
#pragma unroll
                for (int p2 = 0; p2 < 2; ++p2) {
                    uint32_t br[4];
                    uint32_t off = (raw + (uint32_t)s * 2048 +
                                    (uint32_t)(cg * 2 + p2) * 32) ^ xconst;
                    ldsm4t(br, bbuf + off);
#pragma unroll
                    for (int m = 0; m < 2; ++m) {
                        mma16816(acc[m][2 * p2 + 0], af[m][0], af[m][1],
                                 af[m][2], af[m][3], br[0], br[1]);
                        mma16816(acc[m][2 * p2 + 1], af[m][0], af[m][1],
                                 af[m][2], af[m][3], br[2], br[3]);
                    }
                }
            }
        }

        // ---- epilogue: rows rg*32 + m*16 + {g, g+8}, cols cg*32 + p*8 + 2c
#pragma unroll
        for (int m = 0; m < 2; ++m) {
            float* o0 = out + (size_t)(z0 + rg * 32 + m * 16 + g) * 64;
            float* o1 = o0 + 8 * 64;
#pragma unroll
            for (int p = 0; p < 4; ++p) {
                int n = cg * 32 + p * 8 + 2 * c;
                *(float2*)(o0 + n) = make_float2(acc[m][p][0], acc[m][p][1]);
                *(float2*)(o1 + n) = make_float2(acc[m][p][2], acc[m][p][3]);
            }
        }
    }
}

// ---------------- launch ----------------
extern "C" void kernel_launch(void* const* d_in, const int* in_sizes, int n_in,
                              void* d_out, int out_size) {
    (void)n_in; (void)out_size;
    const float* f   = (const float*)d_in[0];   // [Z, 64] fp32
    const float* mix = (const float*)d_in[1];   // [32, 64, 64, 64] fp32
    const float* wgt = (const float*)d_in[2];   // [32] fp32
    float* out = (float*)d_out;                 // [Z, 64] fp32

    cudaFuncSetAttribute(lts_main, cudaFuncAttributeMaxDynamicSharedMemorySize,
                         SMEM_TOTAL);

    lts_prep1<<<2048, 128>>>(mix, wgt);
    lts_prep2<<<(NCHUNK * 4096) / 256, 256>>>();
    lts_main<<<NPERS, NTH, SMEM_TOTAL>>>(f, out);
}

// round 11
// speedup vs baseline: 1.0333x; 1.0333x over previous
#include <cuda_runtime.h>
#include <cuda_fp16.h>
#include <cstdint>
#include <cstring>

// ---------------- constants ----------------
#define ZT      128          // z rows per CTA
#define NTH     256          // 8 warps: 4 row-groups x 2 col-groups (32x32 tiles)
#define NCHUNK  33           // circulant-difference chunks d=0..32

#define FH_STRIDE 208        // bytes per fp16 f row (104 halves, 96 used)

// smem layout (bytes)
#define OFF_B    0                            // 3 x 8KB B ring
#define OFF_F0   24576                        // fp16 f tile (row-doubled)
#define OFF_F1   (24576 + ZT * FH_STRIDE)     // fp16 f tile shifted by one col
#define SMEM_TOTAL (OFF_F1 + ZT * FH_STRIDE)  // 77824

// scratch
__device__ float g_M[4][262144];                             // four w-quarter partials
__device__ __align__(1024) unsigned char g_B[NCHUNK * 8192]; // pre-swizzled fp16 chunks

// ---------------- helpers ----------------
__device__ __forceinline__ uint32_t smem_u32(const void* p) {
    uint32_t a;
    asm("{ .reg .u64 t; cvta.to.shared.u64 t, %1; cvt.u32.u64 %0, t; }"
        : "=r"(a) : "l"(p));
    return a;
}

__device__ __forceinline__ uint32_t h2u(float lo, float hi) {
    __half2 h = __floats2half2_rn(lo, hi);
    uint32_t u;
    memcpy(&u, &h, 4);
    return u;
}

__device__ __forceinline__ uint32_t mulh2(uint32_t a, uint32_t b) {
    uint32_t d;
    asm("mul.rn.f16x2 %0, %1, %2;" : "=r"(d) : "r"(a), "r"(b));
    return d;
}

__device__ __forceinline__ void cpa16(uint32_t s, const void* g) {
    asm volatile("cp.async.cg.shared.global [%0], [%1], 16;" :: "r"(s), "l"(g) : "memory");
}

__device__ __forceinline__ void ldsm4t(uint32_t* r, uint32_t addr) {
    asm volatile(
        "ldmatrix.sync.aligned.m8n8.x4.trans.shared.b16 {%0,%1,%2,%3}, [%4];"
        : "=r"(r[0]), "=r"(r[1]), "=r"(r[2]), "=r"(r[3]) : "r"(addr));
}

__device__ __forceinline__ void mma16816(float* d,
                                         uint32_t a0, uint32_t a1, uint32_t a2, uint32_t a3,
                                         uint32_t b0, uint32_t b1) {
    asm volatile(
        "mma.sync.aligned.m16n8k16.row.col.f32.f16.f16.f32 "
        "{%0,%1,%2,%3}, {%4,%5,%6,%7}, {%8,%9}, {%0,%1,%2,%3};"
        : "+f"(d[0]), "+f"(d[1]), "+f"(d[2]), "+f"(d[3])
        : "r"(a0), "r"(a1), "r"(a2), "r"(a3), "r"(b0), "r"(b1));
}

// ---------------- prep 1: four w-quarter partial sums (MLP-friendly) ----------------
extern "C" __global__ void lts_prep1(const float* __restrict__ mix,
                                     const float* __restrict__ wgt) {
    __shared__ float ws[8];
    const int quarter = blockIdx.x >> 9;        // 0..3
    const int blk     = blockIdx.x & 511;
    if (threadIdx.x < 8) ws[threadIdx.x] = wgt[quarter * 8 + threadIdx.x];
    __syncthreads();

    size_t idx = ((size_t)blk * 128 + threadIdx.x) * 4;
    float4 s = make_float4(0.f, 0.f, 0.f, 0.f);
#pragma unroll
    for (int w = 0; w < 8; ++w) {
        float4 m = __ldg((const float4*)(mix + (size_t)(quarter * 8 + w) * 262144 + idx));
        float c = ws[w];
        s.x += c * m.x; s.y += c * m.y; s.z += c * m.z; s.w += c * m.w;
    }
    *(float4*)(&g_M[quarter][idx]) = s;
}

// ---------------- prep 2: fold symmetric pairs, fp16 swizzled ----------------
extern "C" __global__ void lts_prep2() {
    int t = blockIdx.x * 256 + threadIdx.x;     // < 33*4096
    int d = t >> 12;
    int rem = t & 4095;
    int c = rem >> 6;
    int k = rem & 63;
    int j2 = (c + d) & 63;

    int i1 = k * 4096 + c * 64 + j2;
    int i2 = k * 4096 + j2 * 64 + c;
    float v = (g_M[0][i1] + g_M[1][i1]) + (g_M[2][i1] + g_M[3][i1]);
    if (d > 0) v += (g_M[0][i2] + g_M[1][i2]) + (g_M[2][i2] + g_M[3][i2]);
    if (d == 32) v *= 0.5f;

    unsigned short h;
    {
        __half hh = __float2half_rn(v);
        memcpy(&h, &hh, 2);
    }
    uint32_t off = (uint32_t)c * 128 + (uint32_t)k * 2;
    off ^= ((uint32_t)(c & 7)) << 4;            // SW128-style swizzle
    *(unsigned short*)(g_B + (size_t)d * 8192 + off) = h;
}

// ---------------- main kernel ----------------
extern "C" __global__ void __launch_bounds__(NTH, 2)
lts_main(const float* __restrict__ f, float* __restrict__ out) {
    extern __shared__ __align__(1024) unsigned char smem[];
    const uint32_t sb = smem_u32(smem);

    const int tid  = threadIdx.x;
    const int wid  = tid >> 5;
    const int lane = tid & 31;
    const int z0   = blockIdx.x * ZT;

    const int rg = wid & 3;                   // row group: rows rg*32 .. rg*32+31
    const int cg = wid >> 2;                  // col group: cols cg*32 .. cg*32+31
    const int g  = lane >> 2;                 // row within group 0..7
    const int c  = lane & 3;                  // col pair 0..3

    // ---- prefetch B stages 0,1 early (one commit group each)
#pragma unroll
    for (int s = 0; s < 2; ++s) {
        uint32_t dst = sb + OFF_B + s * 8192 + tid * 32;
        const unsigned char* src = g_B + (size_t)s * 8192 + tid * 32;
        cpa16(dst, src); cpa16(dst + 16, src + 16);
        asm volatile("cp.async.commit_group;" ::: "memory");
    }

    // ---- fill F0: fp16 f tile [ZT x 96] (cols 64..95 duplicate 0..31), pad zero
    {
        const float4* src = (const float4*)(f + (size_t)z0 * 64);
#pragma unroll
        for (int q = 0; q < (ZT * 16) / NTH; ++q) {
            int idx = tid + q * NTH;            // float4 index
            int row = idx >> 4;
            int c4  = idx & 15;
            float4 v = src[idx];
            uint32_t w0 = h2u(v.x, v.y), w1 = h2u(v.z, v.w);
            uint32_t* p = (uint32_t*)(smem + OFF_F0 + row * FH_STRIDE + c4 * 8);
            p[0] = w0; p[1] = w1;
            if (c4 < 8) {
                uint32_t* pd = (uint32_t*)(smem + OFF_F0 + row * FH_STRIDE + 128 + c4 * 8);
                pd[0] = w0; pd[1] = w1;
            }
        }
#pragma unroll
        for (int q = 0; q < (ZT * 4) / NTH; ++q) {
            int idx = tid + q * NTH;
            int row = idx >> 2;
            int w   = idx & 3;
            *(uint32_t*)(smem + OFF_F0 + row * FH_STRIDE + 192 + w * 4) = 0;
        }
    }
    __syncthreads();

    // ---- build F1 (shifted by one half) via funnel shift of F0 words
    {
#pragma unroll
        for (int q = 0; q < (ZT * 48) / NTH; ++q) {
            int idx = tid + q * NTH;
            int row = idx / 48;
            int w   = idx - row * 48;
            const uint32_t* pr = (const uint32_t*)(smem + OFF_F0 + row * FH_STRIDE + w * 4);
            uint32_t a = pr[0], b = pr[1];
            *(uint32_t*)(smem + OFF_F1 + row * FH_STRIDE + w * 4) =
                __funnelshift_r(a, b, 16);
        }
    }

    // fixed factors: half2 at cols (16s+2c, +1) [a] and (+8,+9) [b], 4 rows (2m x 2h)
    uint32_t fja[2][2][4], fjb[2][2][4];
#pragma unroll
    for (int m = 0; m < 2; ++m)
#pragma unroll
        for (int h = 0; h < 2; ++h) {
            int row = rg * 32 + m * 16 + h * 8 + g;
            const unsigned char* bp = smem + OFF_F0 + row * FH_STRIDE + c * 4;
#pragma unroll
            for (int s = 0; s < 4; ++s) {
                fja[m][h][s] = *(const uint32_t*)(bp + s * 32);
                fjb[m][h][s] = *(const uint32_t*)(bp + s * 32 + 16);
            }
        }
    __syncthreads();   // F1 visible

    // ldmatrix address components (buffer-local)
    const uint32_t row_base = (lane & 7) + 8 * ((lane >> 3) & 1);
    const uint32_t n0_base  = 8 * (lane >> 4);
    const uint32_t raw      = row_base * 128 + n0_base * 2;
    const uint32_t xconst   = (row_base & 7) << 4;

    float acc[2][4][4];
#pragma unroll
    for (int m = 0; m < 2; ++m)
#pragma unroll
        for (int p = 0; p < 4; ++p)
#pragma unroll
            for (int e = 0; e < 4; ++e) acc[m][p][e] = 0.f;

    // ---- main chunk loop d = 0..32, 3-stage B ring, one chunk of fetch slack
#pragma unroll 1
    for (int d = 0; d < NCHUNK; ++d) {
        const uint32_t bbuf = sb + OFF_B + (uint32_t)(d % 3) * 8192;

        // stage d ready when at most one younger group remains
        asm volatile("cp.async.wait_group 1;" ::: "memory");
        __syncthreads();

        // prefetch stage d+2 (slot last read in chunk d-1; the barrier above fences it)
        if (d + 2 < NCHUNK) {
            uint32_t dst = sb + OFF_B + (uint32_t)((d + 2) % 3) * 8192 + tid * 32;
            const unsigned char* src = g_B + (size_t)(d + 2) * 8192 + tid * 32;
            cpa16(dst, src); cpa16(dst + 16, src + 16);
        }
        asm volatile("cp.async.commit_group;" ::: "memory");  // (possibly empty) keeps count aligned

        const int off_tile = (d & 1) ? (OFF_F1 + (d - 1) * 2) : (OFF_F0 + d * 2);
        const unsigned char* u0base = smem + off_tile + (rg * 32 + g) * FH_STRIDE + c * 4;

        // per k-step: produce A fragments (8 LDS + 8 HMUL2), 2 ldmatrix, 8 MMA
#pragma unroll
        for (int s = 0; s < 4; ++s) {
            uint32_t af[2][4];
#pragma unroll
            for (int m = 0; m < 2; ++m) {
                const unsigned char* u0 = u0base + m * (16 * FH_STRIDE) + s * 32;
                const unsigned char* u1 = u0 + 8 * FH_STRIDE;
                af[m][0] = mulh2(fja[m][0][s], *(const uint32_t*)(u0));
                af[m][1] = mulh2(fja[m][1][s], *(const uint32_t*)(u1));
                af[m][2] = mulh2(fjb[m][0][s], *(const uint32_t*)(u0 + 16));
                af[m][3] = mulh2(fjb[m][1][s], *(const uint32_t*)(u1 + 16));
            }
#pragma unroll
            for (int p2 = 0; p2 < 2; ++p2) {
                uint32_t br[4];
                uint32_t off = (raw + (uint32_t)s * 2048 +
                                (uint32_t)(cg * 2 + p2) * 32) ^ xconst;
                ldsm4t(br, bbuf + off);
#pragma unroll
                for (int m = 0; m < 2; ++m) {
                    mma16816(acc[m][2 * p2 + 0], af[m][0], af[m][1],
                             af[m][2], af[m][3], br[0], br[1]);
                    mma16816(acc[m][2 * p2 + 1], af[m][0], af[m][1],
                             af[m][2], af[m][3], br[2], br[3]);
                }
            }
        }
    }

    // ---- epilogue: rows rg*32 + m*16 + {g, g+8}, cols cg*32 + p*8 + 2c
#pragma unroll
    for (int m = 0; m < 2; ++m) {
        float* o0 = out + (size_t)(z0 + rg * 32 + m * 16 + g) * 64;
        float* o1 = o0 + 8 * 64;
#pragma unroll
        for (int p = 0; p < 4; ++p) {
            int n = cg * 32 + p * 8 + 2 * c;
            *(float2*)(o0 + n) = make_float2(acc[m][p][0], acc[m][p][1]);
            *(float2*)(o1 + n) = make_float2(acc[m][p][2], acc[m][p][3]);
        }
    }
}

// ---------------- launch ----------------
extern "C" void kernel_launch(void* const* d_in, const int* in_sizes, int n_in,
                              void* d_out, int out_size) {
    (void)n_in; (void)out_size;
    const float* f   = (const float*)d_in[0];   // [Z, 64] fp32
    const float* mix = (const float*)d_in[1];   // [32, 64, 64, 64] fp32
    const float* wgt = (const float*)d_in[2];   // [32] fp32
    float* out = (float*)d_out;                 // [Z, 64] fp32

    const int Z = in_sizes[0] / 64;

    cudaFuncSetAttribute(lts_main, cudaFuncAttributeMaxDynamicSharedMemorySize,
                         SMEM_TOTAL);

    lts_prep1<<<2048, 128>>>(mix, wgt);
    lts_prep2<<<(NCHUNK * 4096) / 256, 256>>>();
    lts_main<<<Z / ZT, NTH, SMEM_TOTAL>>>(f, out);
}